// round 12
// baseline (speedup 1.0000x reference)
#include <cuda_runtime.h>
#include <cstdint>
#include <cstddef>

// ---------------------------------------------------------------------------
// ScalEdgesRead: out[b,e,:] = (hs[b,src[e],:] + hd[b,dst[e],:]) * 1/sqrt(2)
//   hs = x @ W_src^T, hd = x @ W_dst^T     (B=2, N=50000, E=800000, D=64)
// Phase 1: node transform (small SGEMM, M=B*N, K=64, Nout=128 concat)
// Phase 2: edge gather-add-scale (memory bound)
// NOTE: src/dst arrive as int32 (JAX x64 disabled demotes jnp.int64).
// ---------------------------------------------------------------------------

#define INV_SQRT_2 0.70710678118654752440f

// Scratch: hs/hd, 64 floats per (b,n) row. M = B*N = 100000 rows here.
static constexpr int MAX_M = 100352;  // >= 100000, multiple of 64
__device__ float g_hs[(size_t)MAX_M * 64];
__device__ float g_hd[(size_t)MAX_M * 64];

// ---------------------------------------------------------------------------
// Phase 1: 64-row x 128-col tile per block, 128 threads, 8x8 outputs/thread.
// Xs: [64 rows][64 k] (16 KB), Ws: [64 k][128 j] transposed (32 KB) = 48 KB.
// ---------------------------------------------------------------------------
__global__ __launch_bounds__(128) void transform_kernel(
    const float* __restrict__ x,
    const float* __restrict__ Wsrc,   // (64, 64) row-major: W[j*64 + k]
    const float* __restrict__ Wdst,
    int M)
{
    __shared__ float Xs[64][64];
    __shared__ float Ws[64][128];     // Ws[k][j]; j<64 -> Wsrc, j>=64 -> Wdst

    const int tid  = threadIdx.x;
    const int row0 = blockIdx.x * 64;

    // Load W transposed into shared (one-time, tiny).
    for (int idx = tid; idx < 128 * 64; idx += 128) {
        int j = idx >> 6;
        int k = idx & 63;
        float v = (j < 64) ? Wsrc[j * 64 + k] : Wdst[(j - 64) * 64 + k];
        Ws[k][j] = v;
    }
    // Load X tile (float4, coalesced).
    for (int idx = tid; idx < 64 * 16; idx += 128) {
        int r  = idx >> 4;
        int c4 = idx & 15;
        int gr = row0 + r;
        float4 v = make_float4(0.f, 0.f, 0.f, 0.f);
        if (gr < M) v = reinterpret_cast<const float4*>(x)[(size_t)gr * 16 + c4];
        *reinterpret_cast<float4*>(&Xs[r][c4 * 4]) = v;
    }
    __syncthreads();

    const int tx = tid & 15;          // column group: 16 groups of 8 cols
    const int ty = tid >> 4;          // row group:     8 groups of 8 rows
    const int rb = ty * 8;
    const int cb = tx * 8;

    float acc[8][8];
#pragma unroll
    for (int i = 0; i < 8; ++i)
#pragma unroll
        for (int j = 0; j < 8; ++j) acc[i][j] = 0.f;

#pragma unroll 4
    for (int k = 0; k < 64; ++k) {
        float a[8];
#pragma unroll
        for (int i = 0; i < 8; ++i) a[i] = Xs[rb + i][k];
        float4 b0 = *reinterpret_cast<const float4*>(&Ws[k][cb]);
        float4 b1 = *reinterpret_cast<const float4*>(&Ws[k][cb + 4]);
        float bv[8] = {b0.x, b0.y, b0.z, b0.w, b1.x, b1.y, b1.z, b1.w};
#pragma unroll
        for (int i = 0; i < 8; ++i)
#pragma unroll
            for (int j = 0; j < 8; ++j)
                acc[i][j] = fmaf(a[i], bv[j], acc[i][j]);
    }

    // Write: tx<8 -> hs cols [cb, cb+8), tx>=8 -> hd cols [cb-64, cb-56)
    float* outbuf = (tx < 8) ? g_hs : g_hd;
    const int ccol = (tx < 8) ? cb : (cb - 64);
#pragma unroll
    for (int i = 0; i < 8; ++i) {
        int gr = row0 + rb + i;
        if (gr < M) {
            float* p = outbuf + (size_t)gr * 64 + ccol;
            *reinterpret_cast<float4*>(p)     = make_float4(acc[i][0], acc[i][1], acc[i][2], acc[i][3]);
            *reinterpret_cast<float4*>(p + 4) = make_float4(acc[i][4], acc[i][5], acc[i][6], acc[i][7]);
        }
    }
}

// ---------------------------------------------------------------------------
// Phase 2: one 16-thread group per output row (b,e); float4 per thread.
// 256 threads/block = 16 rows/block. Indices staged through shared.
// ---------------------------------------------------------------------------
__global__ __launch_bounds__(256) void gather_kernel(
    const int* __restrict__ src,
    const int* __restrict__ dst,
    float* __restrict__ out,
    int E, int N, long long total_rows)
{
    __shared__ int s_idx[2][16];      // [0]=src node, [1]=dst node per row

    const long long row0 = (long long)blockIdx.x * 16;
    const int t = threadIdx.x;

    if (t < 32) {
        int i = t & 15;
        long long row = row0 + i;
        if (row < total_rows) {
            int e = (int)(row % (long long)E);
            s_idx[t >> 4][i] = (t < 16) ? src[e] : dst[e];
        }
    }
    __syncthreads();

    const int i = t >> 4;             // row within block
    const int c = t & 15;             // float4 chunk within row (D=64 -> 16 f4)
    const long long row = row0 + i;
    if (row >= total_rows) return;

    const int b = (int)(row / (long long)E);
    const int sn = s_idx[0][i];
    const int dn = s_idx[1][i];

    const float4* hs4 = reinterpret_cast<const float4*>(g_hs);
    const float4* hd4 = reinterpret_cast<const float4*>(g_hd);

    float4 a = hs4[((size_t)b * N + sn) * 16 + c];
    float4 d = hd4[((size_t)b * N + dn) * 16 + c];

    float4 o;
    o.x = (a.x + d.x) * INV_SQRT_2;
    o.y = (a.y + d.y) * INV_SQRT_2;
    o.z = (a.z + d.z) * INV_SQRT_2;
    o.w = (a.w + d.w) * INV_SQRT_2;

    // Streaming store: evict-first so hs/hd stay L2-resident.
    __stcs(reinterpret_cast<float4*>(out) + (size_t)row * 16 + c, o);
}

// ---------------------------------------------------------------------------
extern "C" void kernel_launch(void* const* d_in, const int* in_sizes, int n_in,
                              void* d_out, int out_size)
{
    const float* x    = (const float*)d_in[0];   // (B, N, 64)
    const int*   src  = (const int*)d_in[1];     // (E,) int32
    const int*   dst  = (const int*)d_in[2];     // (E,) int32
    const float* Wsrc = (const float*)d_in[3];   // (64, 64)
    const float* Wdst = (const float*)d_in[4];   // (64, 64)

    const int D = 64;
    const int E = in_sizes[1];
    const int M = in_sizes[0] / D;                        // B*N
    const long long total_rows = (long long)out_size / D; // B*E
    const int B = (int)(total_rows / E);
    const int N = M / B;

    // Phase 1: node transform
    {
        int grid = (M + 63) / 64;
        transform_kernel<<<grid, 128>>>(x, Wsrc, Wdst, M);
    }
    // Phase 2: edge gather
    {
        long long blocks = (total_rows + 15) / 16;
        gather_kernel<<<(unsigned)blocks, 256>>>(src, dst, (float*)d_out, E, N, total_rows);
    }
}

// round 13
// speedup vs baseline: 1.2056x; 1.2056x over previous
#include <cuda_runtime.h>
#include <cstdint>
#include <cstddef>

// ---------------------------------------------------------------------------
// ScalEdgesRead: out[b,e,:] = (hs[b,src[e],:] + hd[b,dst[e],:]) * 1/sqrt(2)
//   hs = x @ W_src^T, hd = x @ W_dst^T     (B=2, N=50000, E=800000, D=64)
// Phase 1: node transform (small SGEMM, M=B*N, K=64, Nout=128 concat)
// Phase 2: edge gather-add-scale (latency/L2 bound -> maximize MLP)
// NOTE: src/dst arrive as int32 (JAX x64 disabled demotes jnp.int64).
// ---------------------------------------------------------------------------

#define INV_SQRT_2 0.70710678118654752440f

// Scratch: hs/hd, 64 floats per (b,n) row. M = B*N = 100000 rows here.
static constexpr int MAX_M = 100352;  // >= 100000, multiple of 64
__device__ float g_hs[(size_t)MAX_M * 64];
__device__ float g_hd[(size_t)MAX_M * 64];

// ---------------------------------------------------------------------------
// Phase 1: 64-row x 128-col tile per block, 128 threads, 8x8 outputs/thread.
// Xs: [64 rows][64 k] (16 KB), Ws: [64 k][128 j] transposed (32 KB) = 48 KB.
// __launch_bounds__(128, 4): force 4 blocks/SM (16 warps) so the FMA pipe
// stays fed across LDS latency; caps regs at 128/thread (no spills with
// unroll 2 + float2 A-loads).
// ---------------------------------------------------------------------------
__global__ __launch_bounds__(128, 4) void transform_kernel(
    const float* __restrict__ x,
    const float* __restrict__ Wsrc,   // (64, 64) row-major: W[j*64 + k]
    const float* __restrict__ Wdst,
    int M)
{
    __shared__ float Xs[64][64];
    __shared__ float Ws[64][128];     // Ws[k][j]; j<64 -> Wsrc, j>=64 -> Wdst

    const int tid  = threadIdx.x;
    const int row0 = blockIdx.x * 64;

    // Load W transposed into shared (one-time, tiny).
    for (int idx = tid; idx < 128 * 64; idx += 128) {
        int j = idx >> 6;
        int k = idx & 63;
        float v = (j < 64) ? Wsrc[j * 64 + k] : Wdst[(j - 64) * 64 + k];
        Ws[k][j] = v;
    }
    // Load X tile (float4, coalesced).
    for (int idx = tid; idx < 64 * 16; idx += 128) {
        int r  = idx >> 4;
        int c4 = idx & 15;
        int gr = row0 + r;
        float4 v = make_float4(0.f, 0.f, 0.f, 0.f);
        if (gr < M) v = reinterpret_cast<const float4*>(x)[(size_t)gr * 16 + c4];
        *reinterpret_cast<float4*>(&Xs[r][c4 * 4]) = v;
    }
    __syncthreads();

    const int tx = tid & 15;          // column group: 16 groups of 8 cols
    const int ty = tid >> 4;          // row group:     8 groups of 8 rows
    const int rb = ty * 8;
    const int cb = tx * 8;

    float acc[8][8];
#pragma unroll
    for (int i = 0; i < 8; ++i)
#pragma unroll
        for (int j = 0; j < 8; ++j) acc[i][j] = 0.f;

#pragma unroll 2
    for (int k = 0; k < 64; k += 2) {
        // A: two k's per row with one LDS.64 each (halves scalar-LDS count).
        float2 a2[8];
#pragma unroll
        for (int i = 0; i < 8; ++i)
            a2[i] = *reinterpret_cast<const float2*>(&Xs[rb + i][k]);

#pragma unroll
        for (int kk = 0; kk < 2; ++kk) {
            float4 b0 = *reinterpret_cast<const float4*>(&Ws[k + kk][cb]);
            float4 b1 = *reinterpret_cast<const float4*>(&Ws[k + kk][cb + 4]);
            float bv[8] = {b0.x, b0.y, b0.z, b0.w, b1.x, b1.y, b1.z, b1.w};
#pragma unroll
            for (int i = 0; i < 8; ++i) {
                float av = kk ? a2[i].y : a2[i].x;
#pragma unroll
                for (int j = 0; j < 8; ++j)
                    acc[i][j] = fmaf(av, bv[j], acc[i][j]);
            }
        }
    }

    // Write: tx<8 -> hs cols [cb, cb+8), tx>=8 -> hd cols [cb-64, cb-56)
    float* outbuf = (tx < 8) ? g_hs : g_hd;
    const int ccol = (tx < 8) ? cb : (cb - 64);
#pragma unroll
    for (int i = 0; i < 8; ++i) {
        int gr = row0 + rb + i;
        if (gr < M) {
            float* p = outbuf + (size_t)gr * 64 + ccol;
            *reinterpret_cast<float4*>(p)     = make_float4(acc[i][0], acc[i][1], acc[i][2], acc[i][3]);
            *reinterpret_cast<float4*>(p + 4) = make_float4(acc[i][4], acc[i][5], acc[i][6], acc[i][7]);
        }
    }
}

// ---------------------------------------------------------------------------
// Phase 2: 256 threads/block, 4 rows per thread (64 rows/block).
// Each thread: 16-lane row group, one float4 per row. All 8 index loads and
// 8 gather loads are independent -> deep MLP, no __syncthreads, no smem.
// ---------------------------------------------------------------------------
__global__ __launch_bounds__(256) void gather_kernel(
    const int* __restrict__ src,
    const int* __restrict__ dst,
    float* __restrict__ out,
    int E, int N, long long total_rows)
{
    const int t = threadIdx.x;
    const int i = t >> 4;             // row slot within block tile (0..15)
    const int c = t & 15;             // float4 chunk within row (D=64 -> 16 f4)
    const long long base = (long long)blockIdx.x * 64 + i;

    const float4* hs4 = reinterpret_cast<const float4*>(g_hs);
    const float4* hd4 = reinterpret_cast<const float4*>(g_hd);

    float4 a[4], d[4];
    long long rows[4];
    bool val[4];

#pragma unroll
    for (int r = 0; r < 4; ++r) {
        long long row = base + (long long)r * 16;
        rows[r] = row;
        val[r] = (row < total_rows);
        if (val[r]) {
            long long e = row;
            int b = 0;
            while (e >= (long long)E) { e -= (long long)E; ++b; }  // B small (=2)
            int sn = __ldg(src + e);   // 16 lanes same addr -> broadcast
            int dn = __ldg(dst + e);
            a[r] = hs4[((size_t)b * N + sn) * 16 + c];
            d[r] = hd4[((size_t)b * N + dn) * 16 + c];
        }
    }

#pragma unroll
    for (int r = 0; r < 4; ++r) {
        if (val[r]) {
            float4 o;
            o.x = (a[r].x + d[r].x) * INV_SQRT_2;
            o.y = (a[r].y + d[r].y) * INV_SQRT_2;
            o.z = (a[r].z + d[r].z) * INV_SQRT_2;
            o.w = (a[r].w + d[r].w) * INV_SQRT_2;
            // Streaming store: evict-first so hs/hd stay L2-resident.
            __stcs(reinterpret_cast<float4*>(out) + (size_t)rows[r] * 16 + c, o);
        }
    }
}

// ---------------------------------------------------------------------------
extern "C" void kernel_launch(void* const* d_in, const int* in_sizes, int n_in,
                              void* d_out, int out_size)
{
    const float* x    = (const float*)d_in[0];   // (B, N, 64)
    const int*   src  = (const int*)d_in[1];     // (E,) int32
    const int*   dst  = (const int*)d_in[2];     // (E,) int32
    const float* Wsrc = (const float*)d_in[3];   // (64, 64)
    const float* Wdst = (const float*)d_in[4];   // (64, 64)

    const int D = 64;
    const int E = in_sizes[1];
    const int M = in_sizes[0] / D;                        // B*N
    const long long total_rows = (long long)out_size / D; // B*E
    const int B = (int)(total_rows / E);
    const int N = M / B;

    // Phase 1: node transform
    {
        int grid = (M + 63) / 64;
        transform_kernel<<<grid, 128>>>(x, Wsrc, Wdst, M);
    }
    // Phase 2: edge gather (64 rows per block)
    {
        long long blocks = (total_rows + 63) / 64;
        gather_kernel<<<(unsigned)blocks, 256>>>(src, dst, (float*)d_out, E, N, total_rows);
    }
}

// round 14
// speedup vs baseline: 1.2081x; 1.0021x over previous
#include <cuda_runtime.h>
#include <cstdint>
#include <cstddef>

// ---------------------------------------------------------------------------
// ScalEdgesRead: out[b,e,:] = (hs[b,src[e],:] + hd[b,dst[e],:]) * 1/sqrt(2)
//   hs = x @ W_src^T, hd = x @ W_dst^T     (B=2, N=50000, E=800000, D=64)
// Phase 1: node transform via packed fp32 FMA (fma.rn.f32x2) — 2 FLOP/issue.
// Phase 2: edge gather-add-scale (latency/L2 bound -> deep MLP).
// NOTE: src/dst arrive as int32 (JAX x64 disabled demotes jnp.int64).
// ---------------------------------------------------------------------------

#define INV_SQRT_2 0.70710678118654752440f

#define FMA_F32X2(d, a, b, c) \
    asm("fma.rn.f32x2 %0, %1, %2, %3;" : "=l"(d) : "l"(a), "l"(b), "l"(c))

// Scratch: hs/hd, 64 floats per (b,n) row. M = B*N = 100000 rows here.
static constexpr int MAX_M = 100352;  // >= 100000, multiple of 64
__device__ float g_hs[(size_t)MAX_M * 64];
__device__ float g_hd[(size_t)MAX_M * 64];

// ---------------------------------------------------------------------------
// Phase 1: 64-row x 128-col tile per block, 128 threads, 8 rows x 8 cols each.
// Dynamic smem (64 KB): Xd [64 rows][64 k] float2 DUPLICATED ({x,x}) so the
// broadcast A-operand of fma.rn.f32x2 comes straight from one LDS.64;
// Ws [64 k][128 j] so adjacent column pairs come packed from LDS.128.
// Inner loop: 8 LDS.64 + 2 LDS.128 + 32 FFMA2 per k = 42 issues / 128 FLOPs.
// ---------------------------------------------------------------------------
__global__ __launch_bounds__(128) void transform_kernel(
    const float* __restrict__ x,
    const float* __restrict__ Wsrc,   // (64, 64) row-major: W[j*64 + k]
    const float* __restrict__ Wdst,
    int M)
{
    extern __shared__ char smem[];
    float2* Xd = reinterpret_cast<float2*>(smem);                 // [64][64], 32 KB
    float*  Ws = reinterpret_cast<float*>(smem + 32 * 1024);      // [64][128], 32 KB

    const int tid  = threadIdx.x;
    const int row0 = blockIdx.x * 64;

    // Load W transposed into shared: Ws[k*128 + j].
    for (int idx = tid; idx < 128 * 64; idx += 128) {
        int j = idx >> 6;
        int k = idx & 63;
        float v = (j < 64) ? Wsrc[j * 64 + k] : Wdst[(j - 64) * 64 + k];
        Ws[k * 128 + j] = v;
    }
    // Load X tile (float4, coalesced) and store duplicated {x,x}.
    for (int idx = tid; idx < 64 * 16; idx += 128) {
        int r  = idx >> 4;
        int c4 = idx & 15;
        int gr = row0 + r;
        float4 v = make_float4(0.f, 0.f, 0.f, 0.f);
        if (gr < M) v = reinterpret_cast<const float4*>(x)[(size_t)gr * 16 + c4];
        float2* p = &Xd[r * 64 + c4 * 4];
        p[0] = make_float2(v.x, v.x);
        p[1] = make_float2(v.y, v.y);
        p[2] = make_float2(v.z, v.z);
        p[3] = make_float2(v.w, v.w);
    }
    __syncthreads();

    const int tx = tid & 15;          // column group: 16 groups of 8 cols
    const int ty = tid >> 4;          // row group:     8 groups of 8 rows
    const int rb = ty * 8;
    const int cb = tx * 8;

    unsigned long long acc2[8][4];    // [row][col-pair], f32x2 accumulators
#pragma unroll
    for (int i = 0; i < 8; ++i)
#pragma unroll
        for (int p = 0; p < 4; ++p) acc2[i][p] = 0ull;

#pragma unroll 4
    for (int k = 0; k < 64; ++k) {
        unsigned long long aa[8];
#pragma unroll
        for (int i = 0; i < 8; ++i)
            aa[i] = *reinterpret_cast<const unsigned long long*>(&Xd[(rb + i) * 64 + k]);

        // Column pairs (w_j, w_j+1): two 16-byte LDS give 4 packed pairs.
        ulonglong2 bq0 = *reinterpret_cast<const ulonglong2*>(&Ws[k * 128 + cb]);
        ulonglong2 bq1 = *reinterpret_cast<const ulonglong2*>(&Ws[k * 128 + cb + 4]);

#pragma unroll
        for (int i = 0; i < 8; ++i) {
            FMA_F32X2(acc2[i][0], aa[i], bq0.x, acc2[i][0]);
            FMA_F32X2(acc2[i][1], aa[i], bq0.y, acc2[i][1]);
            FMA_F32X2(acc2[i][2], aa[i], bq1.x, acc2[i][2]);
            FMA_F32X2(acc2[i][3], aa[i], bq1.y, acc2[i][3]);
        }
    }

    // Write: tx<8 -> hs cols [cb, cb+8), tx>=8 -> hd cols [cb-64, cb-56)
    float* outbuf = (tx < 8) ? g_hs : g_hd;
    const int ccol = (tx < 8) ? cb : (cb - 64);
#pragma unroll
    for (int i = 0; i < 8; ++i) {
        int gr = row0 + rb + i;
        if (gr < M) {
            float4 o0, o1;
            o0.x = __uint_as_float((unsigned)(acc2[i][0] & 0xffffffffull));
            o0.y = __uint_as_float((unsigned)(acc2[i][0] >> 32));
            o0.z = __uint_as_float((unsigned)(acc2[i][1] & 0xffffffffull));
            o0.w = __uint_as_float((unsigned)(acc2[i][1] >> 32));
            o1.x = __uint_as_float((unsigned)(acc2[i][2] & 0xffffffffull));
            o1.y = __uint_as_float((unsigned)(acc2[i][2] >> 32));
            o1.z = __uint_as_float((unsigned)(acc2[i][3] & 0xffffffffull));
            o1.w = __uint_as_float((unsigned)(acc2[i][3] >> 32));
            float* p = outbuf + (size_t)gr * 64 + ccol;
            *reinterpret_cast<float4*>(p)     = o0;
            *reinterpret_cast<float4*>(p + 4) = o1;
        }
    }
}

// ---------------------------------------------------------------------------
// Phase 2: 256 threads/block, 4 rows per thread (64 rows/block).
// Each thread: 16-lane row group, one float4 per row. All 8 index loads and
// 8 gather loads are independent -> deep MLP, no __syncthreads, no smem.
// ---------------------------------------------------------------------------
__global__ __launch_bounds__(256) void gather_kernel(
    const int* __restrict__ src,
    const int* __restrict__ dst,
    float* __restrict__ out,
    int E, int N, long long total_rows)
{
    const int t = threadIdx.x;
    const int i = t >> 4;             // row slot within block tile (0..15)
    const int c = t & 15;             // float4 chunk within row (D=64 -> 16 f4)
    const long long base = (long long)blockIdx.x * 64 + i;

    const float4* hs4 = reinterpret_cast<const float4*>(g_hs);
    const float4* hd4 = reinterpret_cast<const float4*>(g_hd);

    float4 a[4], d[4];
    long long rows[4];
    bool val[4];

#pragma unroll
    for (int r = 0; r < 4; ++r) {
        long long row = base + (long long)r * 16;
        rows[r] = row;
        val[r] = (row < total_rows);
        if (val[r]) {
            long long e = row;
            int b = 0;
            while (e >= (long long)E) { e -= (long long)E; ++b; }  // B small (=2)
            int sn = __ldg(src + e);   // 16 lanes same addr -> broadcast
            int dn = __ldg(dst + e);
            a[r] = hs4[((size_t)b * N + sn) * 16 + c];
            d[r] = hd4[((size_t)b * N + dn) * 16 + c];
        }
    }

#pragma unroll
    for (int r = 0; r < 4; ++r) {
        if (val[r]) {
            float4 o;
            o.x = (a[r].x + d[r].x) * INV_SQRT_2;
            o.y = (a[r].y + d[r].y) * INV_SQRT_2;
            o.z = (a[r].z + d[r].z) * INV_SQRT_2;
            o.w = (a[r].w + d[r].w) * INV_SQRT_2;
            // Streaming store: evict-first so hs/hd stay L2-resident.
            __stcs(reinterpret_cast<float4*>(out) + (size_t)rows[r] * 16 + c, o);
        }
    }
}

// ---------------------------------------------------------------------------
extern "C" void kernel_launch(void* const* d_in, const int* in_sizes, int n_in,
                              void* d_out, int out_size)
{
    const float* x    = (const float*)d_in[0];   // (B, N, 64)
    const int*   src  = (const int*)d_in[1];     // (E,) int32
    const int*   dst  = (const int*)d_in[2];     // (E,) int32
    const float* Wsrc = (const float*)d_in[3];   // (64, 64)
    const float* Wdst = (const float*)d_in[4];   // (64, 64)

    const int D = 64;
    const int E = in_sizes[1];
    const int M = in_sizes[0] / D;                        // B*N
    const long long total_rows = (long long)out_size / D; // B*E
    const int B = (int)(total_rows / E);
    const int N = M / B;

    const int SMEM_BYTES = 64 * 1024;   // Xd 32 KB + Ws 32 KB

    // Phase 1: node transform (FFMA2). Attribute set is idempotent and
    // capture-safe (no stream work, no allocation).
    {
        cudaFuncSetAttribute(transform_kernel,
                             cudaFuncAttributeMaxDynamicSharedMemorySize, SMEM_BYTES);
        int grid = (M + 63) / 64;
        transform_kernel<<<grid, 128, SMEM_BYTES>>>(x, Wsrc, Wdst, M);
    }
    // Phase 2: edge gather (64 rows per block)
    {
        long long blocks = (total_rows + 63) / 64;
        gather_kernel<<<(unsigned)blocks, 256>>>(src, dst, (float*)d_out, E, N, total_rows);
    }
}